// round 15
// baseline (speedup 1.0000x reference)
#include <cuda_runtime.h>
#include <cuda_bf16.h>
#include <math.h>

// Seq2Seq LSTM (D=256, H=1024, B=64, 3 layers, 64 enc + 64 dec steps).
// bf16 hi/lo-split mma.sync + cp.async 4-stage ring + cross-phase prefetch.

#define BATCH  64
#define HID    1024
#define FH     4096
#define DIN    256
#define TSTEPS 64
#define PRED   64
#define GRID   128
#define NTHR   256
#define NPHASE (3 * (TSTEPS + PRED))

typedef unsigned int u32;
typedef unsigned long long u64;

// ---------------- static device buffers ----------------
#define WT_ELEMS 47185920ull   // 4096 * (1280 + 5*2048)
__device__ __align__(256) __nv_bfloat16 g_wth[WT_ELEMS];
__device__ __align__(256) __nv_bfloat16 g_wtl[WT_ELEMS];
__device__ __align__(256) __nv_bfloat16 g_xh[TSTEPS * BATCH * DIN];
__device__ __align__(256) __nv_bfloat16 g_xl[TSTEPS * BATCH * DIN];
__device__ __align__(256) __nv_bfloat16 g_hh[2 * 3 * BATCH * HID];
__device__ __align__(256) __nv_bfloat16 g_hl[2 * 3 * BATCH * HID];
__device__ __align__(256) float g_c[3 * BATCH * HID];
__device__ __align__(256) float g_outs[PRED * BATCH * HID];
__device__ unsigned g_barcnt = 0;
__device__ volatile unsigned g_bargen = 0;

struct Params {
    const float *x;
    const float *eWx0, *eWh0, *eWc0, *eb0;
    const float *eWx, *eWh, *eWc, *eb;
    const float *dWx, *dWh, *dWc, *db;
    const float *finW, *finb;
    const float *h0, *c0;
    float *out;
};

// ---------------- helpers ----------------
__device__ __forceinline__ u32 smem_u32(const void *p) {
    u32 a;
    asm("{ .reg .u64 t; cvta.to.shared.u64 t, %1; cvt.u32.u64 %0, t; }" : "=r"(a) : "l"(p));
    return a;
}
__device__ __forceinline__ void ldsm4(u32 *r, u32 a) {
    asm volatile("ldmatrix.sync.aligned.m8n8.x4.shared.b16 {%0,%1,%2,%3}, [%4];"
        : "=r"(r[0]), "=r"(r[1]), "=r"(r[2]), "=r"(r[3]) : "r"(a));
}
__device__ __forceinline__ void mma16816(float *d, const u32 *a, const u32 *b) {
    asm("mma.sync.aligned.m16n8k16.row.col.f32.bf16.bf16.f32 "
        "{%0,%1,%2,%3}, {%4,%5,%6,%7}, {%8,%9}, {%0,%1,%2,%3};"
        : "+f"(d[0]), "+f"(d[1]), "+f"(d[2]), "+f"(d[3])
        : "r"(a[0]), "r"(a[1]), "r"(a[2]), "r"(a[3]), "r"(b[0]), "r"(b[1]));
}
__device__ __forceinline__ void cpa16(u32 dst, const void *src) {
    asm volatile("cp.async.cg.shared.global [%0], [%1], 16;" :: "r"(dst), "l"(src) : "memory");
}
#define CP_COMMIT() asm volatile("cp.async.commit_group;" ::: "memory")
#define CP_WAIT0()  asm volatile("cp.async.wait_group 0;" ::: "memory")
#define CP_WAIT1()  asm volatile("cp.async.wait_group 1;" ::: "memory")
#define CP_WAIT2()  asm volatile("cp.async.wait_group 2;" ::: "memory")

__device__ __forceinline__ void gbar() {
    __threadfence();
    __syncthreads();
    if (threadIdx.x == 0) {
        unsigned gen = g_bargen;
        if (atomicAdd(&g_barcnt, 1u) == GRID - 1) {
            atomicExch(&g_barcnt, 0u);
            __threadfence();
            g_bargen = gen + 1;
        } else {
            while (g_bargen == gen) { __nanosleep(32); }
        }
    }
    __syncthreads();
    __threadfence();
}

__device__ __forceinline__ float sigm(float x) { return 1.0f / (1.0f + expf(-x)); }

// ---------------- conversion kernel (same layout as R14) ----------------
#define WT_ITEMS 5898240u
#define X_ITEMS  131072u
#define H0_ITEMS 24576u

__global__ void conv_kernel(Params p) {
    const u32 id = blockIdx.x * 256u + threadIdx.x;
    if (id < WT_ITEMS) {
        u32 cls, q;
        if (id < 655360u) { cls = 0; q = id; }
        else { u32 t2 = id - 655360u; cls = 1 + (t2 >> 20); q = t2 & 0xFFFFFu; }
        const u32 n  = q & 4095u;
        const u32 k  = (q >> 12) * 8;
        const int Kc = (cls == 0) ? 1280 : 2048;
        const int K1 = (cls == 0) ? 256 : 1024;
        const float *W1, *W2;
        if (cls == 0)      { W1 = p.eWx0; W2 = p.eWh0; }
        else if (cls <= 2) { W1 = p.eWx + (size_t)(cls - 1) * HID * FH;
                             W2 = p.eWh + (size_t)(cls - 1) * HID * FH; }
        else               { W1 = p.dWx + (size_t)(cls - 3) * HID * FH;
                             W2 = p.dWh + (size_t)(cls - 3) * HID * FH; }
        const u32 oc = ((n >> 3) & 3u) * 1024u + (n >> 5) * 8u + (n & 7u);
        u64 offW = (cls == 0) ? 0ull
                 : 4096ull * 1280ull + (u64)(cls - 1) * 4096ull * 2048ull;
        __align__(16) __nv_bfloat16 hh[8], ll[8];
        #pragma unroll
        for (int kk = 0; kk < 8; kk++) {
            const int kr = (int)k + kk;
            const float v = (kr < K1) ? W1[(size_t)kr * FH + oc]
                                      : W2[(size_t)(kr - K1) * FH + oc];
            __nv_bfloat16 h = __float2bfloat16(v);
            hh[kk] = h;
            ll[kk] = __float2bfloat16(v - __bfloat162float(h));
        }
        const u64 o = offW + (u64)n * Kc + k;
        *(uint4 *)&g_wth[o] = *(const uint4 *)hh;
        *(uint4 *)&g_wtl[o] = *(const uint4 *)ll;
    } else if (id < WT_ITEMS + X_ITEMS) {
        const u32 q = id - WT_ITEMS;
        const u32 d8 = q & 31u;
        const u32 b = (q >> 5) & 63u;
        const u32 t = q >> 11;
        const float *src = p.x + ((size_t)b * TSTEPS + t) * DIN + d8 * 8;
        __align__(16) __nv_bfloat16 hh[8], ll[8];
        #pragma unroll
        for (int kk = 0; kk < 8; kk++) {
            const float v = src[kk];
            __nv_bfloat16 h = __float2bfloat16(v);
            hh[kk] = h;
            ll[kk] = __float2bfloat16(v - __bfloat162float(h));
        }
        const size_t o = ((size_t)t * BATCH + b) * DIN + d8 * 8;
        *(uint4 *)&g_xh[o] = *(const uint4 *)hh;
        *(uint4 *)&g_xl[o] = *(const uint4 *)ll;
    } else if (id < WT_ITEMS + X_ITEMS + H0_ITEMS) {
        const u32 q = id - WT_ITEMS - X_ITEMS;
        const u32 j8 = q & 127u;
        const u32 b = (q >> 7) & 63u;
        const u32 l = q >> 13;
        __align__(16) __nv_bfloat16 hh[8], ll[8];
        #pragma unroll
        for (int kk = 0; kk < 8; kk++) {
            const float v = p.h0[l * HID + j8 * 8 + kk];
            __nv_bfloat16 h = __float2bfloat16(v);
            hh[kk] = h;
            ll[kk] = __float2bfloat16(v - __bfloat162float(h));
        }
        const size_t o = ((size_t)l * BATCH + b) * HID + j8 * 8;   // parity 0
        *(uint4 *)&g_hh[o] = *(const uint4 *)hh;
        *(uint4 *)&g_hl[o] = *(const uint4 *)ll;
    } else if (id < WT_ITEMS + X_ITEMS + 2 * H0_ITEMS) {
        const u32 q = id - WT_ITEMS - X_ITEMS - H0_ITEMS;
        const u32 j8 = q & 127u;
        const u32 b = (q >> 7) & 63u;
        const u32 l = q >> 13;
        float4 v0 = *(const float4 *)&p.c0[l * HID + j8 * 8];
        float4 v1 = *(const float4 *)&p.c0[l * HID + j8 * 8 + 4];
        float *dst = &g_c[((size_t)l * BATCH + b) * HID + j8 * 8];
        *(float4 *)dst = v0;
        *(float4 *)(dst + 4) = v1;
    }
}

// ---------------- main persistent kernel ----------------
// 4-stage cp.async ring. Stage: A [128][272B] = 34816 + B [64][272B] = 17408.
// Chunk order per phase: chunks [0,8) = h_self * Wh (prefetchable),
// chunks [8, nc) = input * Wx.
#define RS          272
#define OFF_B       34816u
#define STAGE_BYTES 52224u
#define SMEM_REQ    (4 * 52224)

struct PhaseCtx {
    const __nv_bfloat16 *a1h, *a1l, *a2h, *a2l, *wh, *wl;
    int lda1, K1, Kc, nc;
    const float *bias, *Wc;
};

__device__ __forceinline__ void phase_ctx(int sp, const Params &p, int n0, PhaseCtx &cx) {
    const int step = sp / 3, layer = sp - step * 3, pp = step & 1;
    const int cls = (step < TSTEPS) ? layer : 3 + layer;
    cx.Kc = (cls == 0) ? 1280 : 2048;
    cx.K1 = (cls == 0) ? 256 : 1024;
    cx.nc = 8 + cx.K1 / 128;
    if (step < TSTEPS && layer == 0) {
        cx.a1h = g_xh + (size_t)step * BATCH * DIN;
        cx.a1l = g_xl + (size_t)step * BATCH * DIN;
        cx.lda1 = DIN;
    } else {
        const int src = (step >= TSTEPS && layer == 0) ? (pp * 3 + 2)
                                                       : ((pp ^ 1) * 3 + layer - 1);
        cx.a1h = g_hh + (size_t)src * BATCH * HID;
        cx.a1l = g_hl + (size_t)src * BATCH * HID;
        cx.lda1 = HID;
    }
    cx.a2h = g_hh + (size_t)(pp * 3 + layer) * BATCH * HID;
    cx.a2l = g_hl + (size_t)(pp * 3 + layer) * BATCH * HID;
    u64 offW = (cls == 0) ? 0ull
             : 4096ull * 1280ull + (u64)(cls - 1) * 4096ull * 2048ull;
    cx.wh = g_wth + offW + (u64)n0 * cx.Kc;
    cx.wl = g_wtl + offW + (u64)n0 * cx.Kc;
    if (step < TSTEPS) {
        if (layer == 0) { cx.bias = p.eb0; cx.Wc = p.eWc0; }
        else { cx.bias = p.eb + (size_t)(layer - 1) * 4 * HID;
               cx.Wc   = p.eWc + (size_t)(layer - 1) * 4 * HID; }
    } else {
        cx.bias = p.db + (size_t)layer * 4 * HID;
        cx.Wc   = p.dWc + (size_t)layer * 4 * HID;
    }
}

__device__ __forceinline__ void issue_chunk(const PhaseCtx &cx, int C, u32 stq, int tid) {
    const __nv_bfloat16 *sh, *sl;
    int lda, koff, wk;
    if (C < 8) { sh = cx.a2h; sl = cx.a2l; lda = HID; koff = C * 128; wk = cx.K1 + C * 128; }
    else { sh = cx.a1h; sl = cx.a1l; lda = cx.lda1; koff = (C - 8) * 128; wk = (C - 8) * 128; }
    #pragma unroll
    for (int i = 0; i < 8; i++) {
        const int flat = i * NTHR + tid;
        const int row = flat >> 4, kq = (flat & 15) * 8;
        const __nv_bfloat16 *s = ((row < 64) ? sh : sl)
                               + (size_t)(row & 63) * lda + koff + kq;
        cpa16(stq + (u32)row * RS + (u32)kq * 2u, s);
    }
    #pragma unroll
    for (int i = 0; i < 4; i++) {
        const int flat = i * NTHR + tid;
        const int row = flat >> 4, kq = (flat & 15) * 8;
        const __nv_bfloat16 *s = ((row < 32) ? cx.wh + (size_t)row * cx.Kc
                                             : cx.wl + (size_t)(row - 32) * cx.Kc)
                               + wk + kq;
        cpa16(stq + OFF_B + (u32)row * RS + (u32)kq * 2u, s);
    }
    CP_COMMIT();
}

__global__ void __launch_bounds__(NTHR, 1) lstm_kernel(Params p) {
    extern __shared__ char smraw[];
    const u32 sb0 = smem_u32(smraw);
    const u32 sb = (sb0 + 1023u) & ~1023u;
    char *smc = smraw + (sb - sb0);

    const int tid = threadIdx.x;
    const int wid = tid >> 5;
    const int lane = tid & 31;
    const int bid = blockIdx.x;

    const int grp = wid >> 2;   // k-group 0/1
    const int wm  = wid & 3;    // m-warp: wm0,1 = hi rows 0-63; wm2,3 = lo rows 64-127
    const u32 aoff = (u32)(lane & 15) * RS + (u32)(lane >> 4) * 16u;
    const u32 boff = (u32)(((lane >> 4) << 3) + (lane & 7)) * RS
                   + (u32)((lane >> 3) & 1) * 16u;
    const int j0 = bid * 8;
    const int n0 = bid * 32;

    PhaseCtx cx;
    phase_ctx(0, p, n0, cx);
    u32 gc = 0;
    issue_chunk(cx, 0, sb + ((gc + 0) & 3u) * STAGE_BYTES, tid);
    issue_chunk(cx, 1, sb + ((gc + 1) & 3u) * STAGE_BYTES, tid);

    #pragma unroll 1
    for (int sp = 0; sp < NPHASE; sp++) {
        const int step = sp / 3;
        const int layer = sp - step * 3;
        const int pp = step & 1;
        const int nc = cx.nc;

        float acc[2][8][4];
        #pragma unroll
        for (int mi = 0; mi < 2; mi++)
            #pragma unroll
            for (int nt = 0; nt < 8; nt++)
                #pragma unroll
                for (int q = 0; q < 4; q++) acc[mi][nt][q] = 0.f;

        #pragma unroll 1
        for (int c = 0; c < nc; c++) {
            if (c + 2 < nc)
                issue_chunk(cx, c + 2, sb + ((gc + (u32)c + 2u) & 3u) * STAGE_BYTES, tid);
            const int rem = nc - 1 - c;
            if (rem >= 2) CP_WAIT2();
            else if (rem == 1) CP_WAIT1();
            else CP_WAIT0();
            __syncthreads();

            const u32 smb = sb + ((gc + (u32)c) & 3u) * STAGE_BYTES;
            const u32 ab = smb + (u32)wm * 8704u + aoff;
            const u32 bb = smb + OFF_B + boff;
            #pragma unroll
            for (int ks = 0; ks < 4; ks++) {
                const u32 kk = (u32)(grp * 4 + ks) * 32u;
                u32 af0[4], af1[4];
                ldsm4(af0, ab + kk);
                ldsm4(af1, ab + 4352u + kk);
                if (wm < 2) {
                    u32 bf[4][4];
                    #pragma unroll
                    for (int np = 0; np < 4; np++)
                        ldsm4(bf[np], bb + (u32)np * 4352u + kk);
                    #pragma unroll
                    for (int nt = 0; nt < 8; nt++) {
                        mma16816(acc[0][nt], af0, &bf[nt >> 1][(nt & 1) * 2]);
                        mma16816(acc[1][nt], af1, &bf[nt >> 1][(nt & 1) * 2]);
                    }
                } else {
                    u32 bf[2][4];
                    #pragma unroll
                    for (int np = 0; np < 2; np++)
                        ldsm4(bf[np], bb + (u32)np * 4352u + kk);
                    #pragma unroll
                    for (int nt = 0; nt < 4; nt++) {
                        mma16816(acc[0][nt], af0, &bf[nt >> 1][(nt & 1) * 2]);
                        mma16816(acc[1][nt], af1, &bf[nt >> 1][(nt & 1) * 2]);
                    }
                }
            }
        }

        // ---- Z exchange: slabs in the 2 ring stages the prefetch won't use ----
        __syncthreads();
        float *zA = (float *)(smc + ((gc + (u32)nc + 2u) & 3u) * STAGE_BYTES);
        float *zB = (float *)(smc + ((gc + (u32)nc + 3u) & 3u) * STAGE_BYTES);
        {
            float *zs = (grp == 0) ? zA : zB;
            const int zr0 = wm * 32 + (lane >> 2);
            const int zc0 = (lane & 3) * 2;
            const int ntl = (wm < 2) ? 8 : 4;
            #pragma unroll
            for (int mi = 0; mi < 2; mi++) {
                const int row = zr0 + mi * 16;
                for (int nt = 0; nt < ntl; nt++) {
                    const int col = nt * 8 + zc0;
                    *(float2 *)&zs[row * 66 + col] =
                        make_float2(acc[mi][nt][0], acc[mi][nt][1]);
                    *(float2 *)&zs[(row + 8) * 66 + col] =
                        make_float2(acc[mi][nt][2], acc[mi][nt][3]);
                }
            }
        }
        gc += (u32)nc;
        __syncthreads();

        // ---- cross-phase prefetch (before epilogue + gbar) ----
        if (sp + 1 < NPHASE) {
            PhaseCtx nx;
            phase_ctx(sp + 1, p, n0, nx);
            issue_chunk(nx, 0, sb + ((gc + 0u) & 3u) * STAGE_BYTES, tid);
            issue_chunk(nx, 1, sb + ((gc + 1u) & 3u) * STAGE_BYTES, tid);
            cx = nx;
        }

        // ---- fused gate epilogue ----
        {
            const float *bias = (sp + 1 < NPHASE) ? nullptr : nullptr;  // placeholder
            (void)bias;
            const float *bs, *Wc;
            if (step < TSTEPS) {
                if (layer == 0) { bs = p.eb0; Wc = p.eWc0; }
                else { bs = p.eb + (size_t)(layer - 1) * 4 * HID;
                       Wc = p.eWc + (size_t)(layer - 1) * 4 * HID; }
            } else {
                bs = p.db + (size_t)layer * 4 * HID;
                Wc = p.dWc + (size_t)layer * 4 * HID;
            }
            __nv_bfloat16 *hhp = g_hh + (size_t)((pp ^ 1) * 3 + layer) * BATCH * HID;
            __nv_bfloat16 *hlp = g_hl + (size_t)((pp ^ 1) * 3 + layer) * BATCH * HID;
            float *cb = g_c + (size_t)layer * BATCH * HID;
            float *ob = (step >= TSTEPS && layer == 2)
                ? g_outs + (size_t)(step - TSTEPS) * BATCH * HID : nullptr;
            #pragma unroll
            for (int it = 0; it < 2; it++) {
                const int idx = tid + it * NTHR;
                const int r = idx >> 3;
                const int jj = idx & 7;
                const int hc = j0 + jj;
                float z[4];
                #pragma unroll
                for (int g = 0; g < 4; g++) {
                    const int ch = g * 8 + jj;
                    z[g] = zA[r * 66 + ch] + zA[r * 66 + 32 + ch] + zA[(64 + r) * 66 + ch]
                         + zB[r * 66 + ch] + zB[r * 66 + 32 + ch] + zB[(64 + r) * 66 + ch];
                }
                const float cold = cb[(size_t)r * HID + hc];
                const float zf = z[0] + bs[hc]           + Wc[hc]           * cold;
                const float zi = z[1] + bs[HID + hc]     + Wc[HID + hc]     * cold;
                const float zg = z[2] + bs[2 * HID + hc] + Wc[2 * HID + hc] * cold;
                const float zo = z[3] + bs[3 * HID + hc] + Wc[3 * HID + hc] * cold;
                const float f  = sigm(zf);
                const float ii = sigm(zi);
                const float g  = tanhf(zg);
                const float o  = sigm(zo);
                const float cn = f * cold + ii * g;
                cb[(size_t)r * HID + hc] = cn;
                const float hv = o * tanhf(cn);
                __nv_bfloat16 hb = __float2bfloat16(hv);
                hhp[(size_t)r * HID + hc] = hb;
                hlp[(size_t)r * HID + hc] = __float2bfloat16(hv - __bfloat162float(hb));
                if (ob) ob[(size_t)r * HID + hc] = hv;
            }
        }
        gbar();
    }

    // ---- final: sigmoid(outs @ finW + finb) -> out [4096, 256] ----
    {
        float *shA = (float *)smc;         // [32][68]
        float *shW = shA + 32 * 68;        // [64][68]
        const int row0 = bid * 32;
        const int r  = tid >> 3;
        const int dj = (tid & 7) * 8;
        #pragma unroll 1
        for (int ch = 0; ch < 4; ch++) {
            const int d0 = ch * 64;
            float f[8];
            #pragma unroll
            for (int j = 0; j < 8; j++) f[j] = 0.f;
            #pragma unroll 1
            for (int kb = 0; kb < HID; kb += 64) {
                __syncthreads();
                #pragma unroll
                for (int q = 0; q < 2; q++) {
                    const int quad = tid + q * NTHR;
                    const int ar = quad >> 4, akq = (quad & 15) * 4;
                    *(float4 *)&shA[ar * 68 + akq] =
                        *(const float4 *)&g_outs[(size_t)(row0 + ar) * HID + kb + akq];
                }
                #pragma unroll
                for (int q = 0; q < 4; q++) {
                    const int quad = tid + q * NTHR;
                    const int wr = quad >> 4, wq = (quad & 15) * 4;
                    *(float4 *)&shW[wr * 68 + wq] =
                        *(const float4 *)&p.finW[(size_t)(kb + wr) * DIN + d0 + wq];
                }
                __syncthreads();
                #pragma unroll 8
                for (int k = 0; k < 64; k++) {
                    const float a = shA[r * 68 + k];
                    const float4 w0 = *(const float4 *)&shW[k * 68 + dj];
                    const float4 w1 = *(const float4 *)&shW[k * 68 + dj + 4];
                    f[0] += a * w0.x; f[1] += a * w0.y;
                    f[2] += a * w0.z; f[3] += a * w0.w;
                    f[4] += a * w1.x; f[5] += a * w1.y;
                    f[6] += a * w1.z; f[7] += a * w1.w;
                }
            }
            float *op = p.out + (size_t)(row0 + r) * DIN + d0 + dj;
            #pragma unroll
            for (int j = 0; j < 8; j++)
                op[j] = sigm(f[j] + p.finb[d0 + dj + j]);
        }
    }
}

extern "C" void kernel_launch(void *const *d_in, const int *in_sizes, int n_in,
                              void *d_out, int out_size) {
    (void)in_sizes; (void)n_in; (void)out_size;
    Params p;
    p.x    = (const float *)d_in[0];
    p.eWx0 = (const float *)d_in[1];
    p.eWh0 = (const float *)d_in[2];
    p.eWc0 = (const float *)d_in[3];
    p.eb0  = (const float *)d_in[4];
    p.eWx  = (const float *)d_in[5];
    p.eWh  = (const float *)d_in[6];
    p.eWc  = (const float *)d_in[7];
    p.eb   = (const float *)d_in[8];
    p.dWx  = (const float *)d_in[9];
    p.dWh  = (const float *)d_in[10];
    p.dWc  = (const float *)d_in[11];
    p.db   = (const float *)d_in[12];
    p.finW = (const float *)d_in[13];
    p.finb = (const float *)d_in[14];
    p.h0   = (const float *)d_in[15];
    p.c0   = (const float *)d_in[16];
    p.out  = (float *)d_out;

    conv_kernel<<<23744, 256>>>(p);
    cudaFuncSetAttribute(lstm_kernel,
                         cudaFuncAttributeMaxDynamicSharedMemorySize, SMEM_REQ);
    lstm_kernel<<<GRID, NTHR, SMEM_REQ>>>(p);
}

// round 17
// speedup vs baseline: 1.6934x; 1.6934x over previous
#include <cuda_runtime.h>
#include <cuda_bf16.h>
#include <math.h>

// Seq2Seq LSTM (D=256, H=1024, B=64, 3 layers, 64 enc + 64 dec steps).
// bf16 hi/lo-split mma.sync, LDG->reg->STS double buffer (R14 pipeline),
// 512 threads (16 warps, 4 k-groups), lo-quadrant MMA skip.

#define BATCH  64
#define HID    1024
#define FH     4096
#define DIN    256
#define TSTEPS 64
#define PRED   64
#define GRID   128
#define NTHR   512
#define NPHASE (3 * (TSTEPS + PRED))

typedef unsigned int u32;
typedef unsigned long long u64;

// ---------------- static device buffers ----------------
#define WT_ELEMS 47185920ull   // 4096 * (1280 + 5*2048)
__device__ __align__(256) __nv_bfloat16 g_wth[WT_ELEMS];
__device__ __align__(256) __nv_bfloat16 g_wtl[WT_ELEMS];
__device__ __align__(256) __nv_bfloat16 g_xh[TSTEPS * BATCH * DIN];
__device__ __align__(256) __nv_bfloat16 g_xl[TSTEPS * BATCH * DIN];
__device__ __align__(256) __nv_bfloat16 g_hh[2 * 3 * BATCH * HID];
__device__ __align__(256) __nv_bfloat16 g_hl[2 * 3 * BATCH * HID];
__device__ __align__(256) float g_c[3 * BATCH * HID];
__device__ __align__(256) float g_outs[PRED * BATCH * HID];
__device__ unsigned g_barcnt = 0;
__device__ volatile unsigned g_bargen = 0;

struct Params {
    const float *x;
    const float *eWx0, *eWh0, *eWc0, *eb0;
    const float *eWx, *eWh, *eWc, *eb;
    const float *dWx, *dWh, *dWc, *db;
    const float *finW, *finb;
    const float *h0, *c0;
    float *out;
};

// ---------------- helpers ----------------
__device__ __forceinline__ u32 smem_u32(const void *p) {
    u32 a;
    asm("{ .reg .u64 t; cvta.to.shared.u64 t, %1; cvt.u32.u64 %0, t; }" : "=r"(a) : "l"(p));
    return a;
}
__device__ __forceinline__ void ldsm4(u32 *r, u32 a) {
    asm volatile("ldmatrix.sync.aligned.m8n8.x4.shared.b16 {%0,%1,%2,%3}, [%4];"
        : "=r"(r[0]), "=r"(r[1]), "=r"(r[2]), "=r"(r[3]) : "r"(a));
}
__device__ __forceinline__ void mma16816(float *d, const u32 *a, const u32 *b) {
    asm("mma.sync.aligned.m16n8k16.row.col.f32.bf16.bf16.f32 "
        "{%0,%1,%2,%3}, {%4,%5,%6,%7}, {%8,%9}, {%0,%1,%2,%3};"
        : "+f"(d[0]), "+f"(d[1]), "+f"(d[2]), "+f"(d[3])
        : "r"(a[0]), "r"(a[1]), "r"(a[2]), "r"(a[3]), "r"(b[0]), "r"(b[1]));
}

__device__ __forceinline__ void gbar() {
    __threadfence();
    __syncthreads();
    if (threadIdx.x == 0) {
        unsigned gen = g_bargen;
        if (atomicAdd(&g_barcnt, 1u) == GRID - 1) {
            atomicExch(&g_barcnt, 0u);
            __threadfence();
            g_bargen = gen + 1;
        } else {
            while (g_bargen == gen) { __nanosleep(32); }
        }
    }
    __syncthreads();
    __threadfence();
}

__device__ __forceinline__ float sigm(float x) { return 1.0f / (1.0f + expf(-x)); }

// ---------------- conversion kernel (layout as R14) ----------------
#define WT_ITEMS 5898240u
#define X_ITEMS  131072u
#define H0_ITEMS 24576u

__global__ void conv_kernel(Params p) {
    const u32 id = blockIdx.x * 256u + threadIdx.x;
    if (id < WT_ITEMS) {
        u32 cls, q;
        if (id < 655360u) { cls = 0; q = id; }
        else { u32 t2 = id - 655360u; cls = 1 + (t2 >> 20); q = t2 & 0xFFFFFu; }
        const u32 n  = q & 4095u;
        const u32 k  = (q >> 12) * 8;
        const int Kc = (cls == 0) ? 1280 : 2048;
        const int K1 = (cls == 0) ? 256 : 1024;
        const float *W1, *W2;
        if (cls == 0)      { W1 = p.eWx0; W2 = p.eWh0; }
        else if (cls <= 2) { W1 = p.eWx + (size_t)(cls - 1) * HID * FH;
                             W2 = p.eWh + (size_t)(cls - 1) * HID * FH; }
        else               { W1 = p.dWx + (size_t)(cls - 3) * HID * FH;
                             W2 = p.dWh + (size_t)(cls - 3) * HID * FH; }
        const u32 oc = ((n >> 3) & 3u) * 1024u + (n >> 5) * 8u + (n & 7u);
        u64 offW = (cls == 0) ? 0ull
                 : 4096ull * 1280ull + (u64)(cls - 1) * 4096ull * 2048ull;
        __align__(16) __nv_bfloat16 hh[8], ll[8];
        #pragma unroll
        for (int kk = 0; kk < 8; kk++) {
            const int kr = (int)k + kk;
            const float v = (kr < K1) ? W1[(size_t)kr * FH + oc]
                                      : W2[(size_t)(kr - K1) * FH + oc];
            __nv_bfloat16 h = __float2bfloat16(v);
            hh[kk] = h;
            ll[kk] = __float2bfloat16(v - __bfloat162float(h));
        }
        const u64 o = offW + (u64)n * Kc + k;
        *(uint4 *)&g_wth[o] = *(const uint4 *)hh;
        *(uint4 *)&g_wtl[o] = *(const uint4 *)ll;
    } else if (id < WT_ITEMS + X_ITEMS) {
        const u32 q = id - WT_ITEMS;
        const u32 d8 = q & 31u;
        const u32 b = (q >> 5) & 63u;
        const u32 t = q >> 11;
        const float *src = p.x + ((size_t)b * TSTEPS + t) * DIN + d8 * 8;
        __align__(16) __nv_bfloat16 hh[8], ll[8];
        #pragma unroll
        for (int kk = 0; kk < 8; kk++) {
            const float v = src[kk];
            __nv_bfloat16 h = __float2bfloat16(v);
            hh[kk] = h;
            ll[kk] = __float2bfloat16(v - __bfloat162float(h));
        }
        const size_t o = ((size_t)t * BATCH + b) * DIN + d8 * 8;
        *(uint4 *)&g_xh[o] = *(const uint4 *)hh;
        *(uint4 *)&g_xl[o] = *(const uint4 *)ll;
    } else if (id < WT_ITEMS + X_ITEMS + H0_ITEMS) {
        const u32 q = id - WT_ITEMS - X_ITEMS;
        const u32 j8 = q & 127u;
        const u32 b = (q >> 7) & 63u;
        const u32 l = q >> 13;
        __align__(16) __nv_bfloat16 hh[8], ll[8];
        #pragma unroll
        for (int kk = 0; kk < 8; kk++) {
            const float v = p.h0[l * HID + j8 * 8 + kk];
            __nv_bfloat16 h = __float2bfloat16(v);
            hh[kk] = h;
            ll[kk] = __float2bfloat16(v - __bfloat162float(h));
        }
        const size_t o = ((size_t)l * BATCH + b) * HID + j8 * 8;   // parity 0
        *(uint4 *)&g_hh[o] = *(const uint4 *)hh;
        *(uint4 *)&g_hl[o] = *(const uint4 *)ll;
    } else if (id < WT_ITEMS + X_ITEMS + 2 * H0_ITEMS) {
        const u32 q = id - WT_ITEMS - X_ITEMS - H0_ITEMS;
        const u32 j8 = q & 127u;
        const u32 b = (q >> 7) & 63u;
        const u32 l = q >> 13;
        float4 v0 = *(const float4 *)&p.c0[l * HID + j8 * 8];
        float4 v1 = *(const float4 *)&p.c0[l * HID + j8 * 8 + 4];
        float *dst = &g_c[((size_t)l * BATCH + b) * HID + j8 * 8];
        *(float4 *)dst = v0;
        *(float4 *)(dst + 4) = v1;
    }
}

// ---------------- main persistent kernel ----------------
// Staging per buffer: A [128 rows][272 B] = 34816 + B [64][272 B] = 17408.
// Z exchange (after mainloop, reuses staging region):
//   per k-group g: hi slab [64][66] f32 + lo slab [64][34] f32 = 6400 floats.
#define RS        272
#define OFF_B     34816u
#define BUFSTRIDE 52224u
#define ZGRP      6400
#define ZLO_OFF   4224
#define SMEM_REQ  (2 * 52224 + 1024)

__global__ void __launch_bounds__(NTHR, 1) lstm_kernel(Params p) {
    extern __shared__ char smraw[];
    const u32 sb0 = smem_u32(smraw);
    const u32 sb = (sb0 + 1023u) & ~1023u;
    char *smc = smraw + (sb - sb0);

    const int tid = threadIdx.x;
    const int wid = tid >> 5;
    const int lane = tid & 31;
    const int bid = blockIdx.x;

    const int grp = wid >> 2;     // k-group 0..3
    const int wm  = wid & 3;      // m-warp: 0,1 = A-hi rows; 2,3 = A-lo rows
    const u32 aoff = (u32)(lane & 15) * RS + (u32)(lane >> 4) * 16u;
    const u32 boff = (u32)(((lane >> 4) << 3) + (lane & 7)) * RS
                   + (u32)((lane >> 3) & 1) * 16u;
    const int j0 = bid * 8;       // this CTA's h-column base
    const int n0 = bid * 32;      // this CTA's weight-column base

    gbar();   // conv_kernel done (stream order) + replay determinism

    #pragma unroll 1
    for (int sp = 0; sp < NPHASE; sp++) {
        const int step = sp / 3;
        const int layer = sp - step * 3;
        const int pp = step & 1;
        const int cls = (step < TSTEPS) ? layer : 3 + layer;
        const int Kc  = (cls == 0) ? 1280 : 2048;
        const int nb1 = (cls == 0) ? 2 : 8;
        const int nc  = Kc / 128;

        const __nv_bfloat16 *a1h, *a1l;
        int lda1;
        if (step < TSTEPS && layer == 0) {
            a1h = g_xh + (size_t)step * BATCH * DIN;
            a1l = g_xl + (size_t)step * BATCH * DIN;
            lda1 = DIN;
        } else {
            const int src = (step >= TSTEPS && layer == 0) ? (pp * 3 + 2)
                                                           : ((pp ^ 1) * 3 + layer - 1);
            a1h = g_hh + (size_t)src * BATCH * HID;
            a1l = g_hl + (size_t)src * BATCH * HID;
            lda1 = HID;
        }
        const __nv_bfloat16 *a2h = g_hh + (size_t)(pp * 3 + layer) * BATCH * HID;
        const __nv_bfloat16 *a2l = g_hl + (size_t)(pp * 3 + layer) * BATCH * HID;

        u64 offW = (cls == 0) ? 0ull
                 : 4096ull * 1280ull + (u64)(cls - 1) * 4096ull * 2048ull;
        const __nv_bfloat16 *wh = g_wth + offW + (u64)n0 * Kc;
        const __nv_bfloat16 *wl = g_wtl + offW + (u64)n0 * Kc;

        const float *bias, *Wc;
        if (step < TSTEPS) {
            if (layer == 0) { bias = p.eb0; Wc = p.eWc0; }
            else { bias = p.eb + (size_t)(layer - 1) * 4 * HID;
                   Wc = p.eWc + (size_t)(layer - 1) * 4 * HID; }
        } else {
            bias = p.db + (size_t)layer * 4 * HID;
            Wc = p.dWc + (size_t)layer * 4 * HID;
        }

        float acc[2][8][4];
        #pragma unroll
        for (int mi = 0; mi < 2; mi++)
            #pragma unroll
            for (int nt = 0; nt < 8; nt++)
                #pragma unroll
                for (int q = 0; q < 4; q++) acc[mi][nt][q] = 0.f;

        uint4 ra[4], rb[2];

#define LOADCHUNK(C) do {                                                       \
        const __nv_bfloat16 *sh_, *sl_; int lda_, krel_;                        \
        if ((C) < nb1) { sh_ = a1h; sl_ = a1l; lda_ = lda1; krel_ = (C) * 128; }\
        else { sh_ = a2h; sl_ = a2l; lda_ = HID; krel_ = ((C) - nb1) * 128; }   \
        _Pragma("unroll")                                                       \
        for (int i_ = 0; i_ < 4; i_++) {                                        \
            const int flat_ = i_ * NTHR + tid;                                  \
            const int row_ = flat_ >> 4, kq_ = (flat_ & 15) * 8;                \
            ra[i_] = *(const uint4 *)(((row_ < 64) ? sh_ : sl_)                 \
                        + (size_t)(row_ & 63) * lda_ + krel_ + kq_);            \
        }                                                                       \
        _Pragma("unroll")                                                       \
        for (int i_ = 0; i_ < 2; i_++) {                                        \
            const int flat_ = i_ * NTHR + tid;                                  \
            const int row_ = flat_ >> 4, kq_ = (flat_ & 15) * 8;                \
            const __nv_bfloat16 *ws_ = (row_ < 32)                              \
                ? (wh + (size_t)row_ * Kc) : (wl + (size_t)(row_ - 32) * Kc);   \
            rb[i_] = *(const uint4 *)(ws_ + (size_t)(C) * 128 + kq_);           \
        }                                                                       \
    } while (0)

#define STORECHUNK(B_) do {                                                     \
        char *bb_ = smc + (u32)(B_) * BUFSTRIDE;                                \
        _Pragma("unroll")                                                       \
        for (int i_ = 0; i_ < 4; i_++) {                                        \
            const int flat_ = i_ * NTHR + tid;                                  \
            const int row_ = flat_ >> 4, kq_ = (flat_ & 15) * 8;                \
            *(uint4 *)(bb_ + row_ * RS + kq_ * 2) = ra[i_];                     \
        }                                                                       \
        _Pragma("unroll")                                                       \
        for (int i_ = 0; i_ < 2; i_++) {                                        \
            const int flat_ = i_ * NTHR + tid;                                  \
            const int row_ = flat_ >> 4, kq_ = (flat_ & 15) * 8;                \
            *(uint4 *)(bb_ + OFF_B + row_ * RS + kq_ * 2) = rb[i_];             \
        }                                                                       \
    } while (0)

        LOADCHUNK(0);
        STORECHUNK(0);
        __syncthreads();

        #pragma unroll 1
        for (int c = 0; c < nc; c++) {
            const bool more = (c + 1) < nc;
            if (more) LOADCHUNK(c + 1);
            const u32 smb = sb + (u32)(c & 1) * BUFSTRIDE;
            const u32 ab = smb + (u32)wm * 8704u + aoff;
            const u32 bb = smb + OFF_B + boff;
            #pragma unroll
            for (int ks = 0; ks < 2; ks++) {
                const u32 kk = (u32)(grp * 2 + ks) * 32u;
                u32 af0[4], af1[4];
                ldsm4(af0, ab + kk);
                ldsm4(af1, ab + 4352u + kk);
                if (wm < 2) {
                    u32 bf[4][4];
                    #pragma unroll
                    for (int np = 0; np < 4; np++)
                        ldsm4(bf[np], bb + (u32)np * 4352u + kk);
                    #pragma unroll
                    for (int nt = 0; nt < 8; nt++) {
                        mma16816(acc[0][nt], af0, &bf[nt >> 1][(nt & 1) * 2]);
                        mma16816(acc[1][nt], af1, &bf[nt >> 1][(nt & 1) * 2]);
                    }
                } else {
                    u32 bf[2][4];
                    #pragma unroll
                    for (int np = 0; np < 2; np++)
                        ldsm4(bf[np], bb + (u32)np * 4352u + kk);
                    #pragma unroll
                    for (int nt = 0; nt < 4; nt++) {
                        mma16816(acc[0][nt], af0, &bf[nt >> 1][(nt & 1) * 2]);
                        mma16816(acc[1][nt], af1, &bf[nt >> 1][(nt & 1) * 2]);
                    }
                }
            }
            if (more) { __syncthreads(); STORECHUNK((c + 1) & 1); __syncthreads(); }
        }

        // ---- Z exchange (reuses staging region) ----
        __syncthreads();
        float *zg = (float *)smc + (size_t)grp * ZGRP;
        if (wm < 2) {
            const int row = wm * 32 + (lane >> 2);
            const int col0 = (lane & 3) * 2;
            #pragma unroll
            for (int mi = 0; mi < 2; mi++) {
                const int r = row + mi * 16;
                #pragma unroll
                for (int nt = 0; nt < 8; nt++) {
                    const int col = nt * 8 + col0;
                    *(float2 *)&zg[r * 66 + col] =
                        make_float2(acc[mi][nt][0], acc[mi][nt][1]);
                    *(float2 *)&zg[(r + 8) * 66 + col] =
                        make_float2(acc[mi][nt][2], acc[mi][nt][3]);
                }
            }
        } else {
            const int row = (wm - 2) * 32 + (lane >> 2);
            const int col0 = (lane & 3) * 2;
            #pragma unroll
            for (int mi = 0; mi < 2; mi++) {
                const int r = row + mi * 16;
                #pragma unroll
                for (int nt = 0; nt < 4; nt++) {
                    const int col = nt * 8 + col0;
                    *(float2 *)&zg[ZLO_OFF + r * 34 + col] =
                        make_float2(acc[mi][nt][0], acc[mi][nt][1]);
                    *(float2 *)&zg[ZLO_OFF + (r + 8) * 34 + col] =
                        make_float2(acc[mi][nt][2], acc[mi][nt][3]);
                }
            }
        }
        __syncthreads();

        // ---- fused gate epilogue: 512 threads, 512 (row, hcol) items ----
        {
            __nv_bfloat16 *hhp = g_hh + (size_t)((pp ^ 1) * 3 + layer) * BATCH * HID;
            __nv_bfloat16 *hlp = g_hl + (size_t)((pp ^ 1) * 3 + layer) * BATCH * HID;
            float *cb = g_c + (size_t)layer * BATCH * HID;
            float *ob = (step >= TSTEPS && layer == 2)
                ? g_outs + (size_t)(step - TSTEPS) * BATCH * HID : nullptr;
            const int r = tid >> 3;
            const int jj = tid & 7;
            const int hc = j0 + jj;
            float z[4];
            #pragma unroll
            for (int g = 0; g < 4; g++) z[g] = 0.f;
            const float *zb = (const float *)smc;
            #pragma unroll
            for (int g4 = 0; g4 < 4; g4++) {
                const float *zs = zb + (size_t)g4 * ZGRP;
                #pragma unroll
                for (int g = 0; g < 4; g++) {
                    const int ch = g * 8 + jj;
                    z[g] += zs[r * 66 + ch] + zs[r * 66 + 32 + ch]
                          + zs[ZLO_OFF + r * 34 + ch];
                }
            }
            const float cold = cb[(size_t)r * HID + hc];
            const float zf = z[0] + bias[hc]           + Wc[hc]           * cold;
            const float zi = z[1] + bias[HID + hc]     + Wc[HID + hc]     * cold;
            const float zgg = z[2] + bias[2 * HID + hc] + Wc[2 * HID + hc] * cold;
            const float zo = z[3] + bias[3 * HID + hc] + Wc[3 * HID + hc] * cold;
            const float f  = sigm(zf);
            const float ii = sigm(zi);
            const float g  = tanhf(zgg);
            const float o  = sigm(zo);
            const float cn = f * cold + ii * g;
            cb[(size_t)r * HID + hc] = cn;
            const float hv = o * tanhf(cn);
            __nv_bfloat16 hb = __float2bfloat16(hv);
            hhp[(size_t)r * HID + hc] = hb;
            hlp[(size_t)r * HID + hc] = __float2bfloat16(hv - __bfloat162float(hb));
            if (ob) ob[(size_t)r * HID + hc] = hv;
        }
        gbar();
    }

    // ---- final: sigmoid(outs @ finW + finb) -> out [4096, 256] ----
    {
        float *shA = (float *)smc;         // [32][68]
        float *shW = shA + 32 * 68;        // [64][68]
        const int row0 = bid * 32;
        const int r  = tid >> 4;           // 0..31
        const int dj = (tid & 15) * 4;     // 0..60
        #pragma unroll 1
        for (int ch = 0; ch < 4; ch++) {
            const int d0 = ch * 64;
            float f0 = 0.f, f1 = 0.f, f2 = 0.f, f3 = 0.f;
            #pragma unroll 1
            for (int kb = 0; kb < HID; kb += 64) {
                __syncthreads();
                {   // stage A: 32 rows x 64 k = 512 float4, 1/thread
                    const int ar = tid >> 4, akq = (tid & 15) * 4;
                    *(float4 *)&shA[ar * 68 + akq] =
                        *(const float4 *)&g_outs[(size_t)(row0 + ar) * HID + kb + akq];
                }
                #pragma unroll
                for (int q = 0; q < 2; q++) {   // stage W: 64 x 64 = 1024 float4
                    const int quad = tid + q * NTHR;
                    const int wr = quad >> 4, wq = (quad & 15) * 4;
                    *(float4 *)&shW[wr * 68 + wq] =
                        *(const float4 *)&p.finW[(size_t)(kb + wr) * DIN + d0 + wq];
                }
                __syncthreads();
                #pragma unroll 8
                for (int k = 0; k < 64; k++) {
                    const float a = shA[r * 68 + k];
                    const float4 w = *(const float4 *)&shW[k * 68 + dj];
                    f0 += a * w.x; f1 += a * w.y; f2 += a * w.z; f3 += a * w.w;
                }
            }
            float *op = p.out + (size_t)(row0 + r) * DIN + d0 + dj;
            op[0] = sigm(f0 + p.finb[d0 + dj + 0]);
            op[1] = sigm(f1 + p.finb[d0 + dj + 1]);
            op[2] = sigm(f2 + p.finb[d0 + dj + 2]);
            op[3] = sigm(f3 + p.finb[d0 + dj + 3]);
        }
    }
}

extern "C" void kernel_launch(void *const *d_in, const int *in_sizes, int n_in,
                              void *d_out, int out_size) {
    (void)in_sizes; (void)n_in; (void)out_size;
    Params p;
    p.x    = (const float *)d_in[0];
    p.eWx0 = (const float *)d_in[1];
    p.eWh0 = (const float *)d_in[2];
    p.eWc0 = (const float *)d_in[3];
    p.eb0  = (const float *)d_in[4];
    p.eWx  = (const float *)d_in[5];
    p.eWh  = (const float *)d_in[6];
    p.eWc  = (const float *)d_in[7];
    p.eb   = (const float *)d_in[8];
    p.dWx  = (const float *)d_in[9];
    p.dWh  = (const float *)d_in[10];
    p.dWc  = (const float *)d_in[11];
    p.db   = (const float *)d_in[12];
    p.finW = (const float *)d_in[13];
    p.finb = (const float *)d_in[14];
    p.h0   = (const float *)d_in[15];
    p.c0   = (const float *)d_in[16];
    p.out  = (float *)d_out;

    conv_kernel<<<23744, 256>>>(p);
    cudaFuncSetAttribute(lstm_kernel,
                         cudaFuncAttributeMaxDynamicSharedMemorySize, SMEM_REQ);
    lstm_kernel<<<GRID, NTHR, SMEM_REQ>>>(p);
}